// round 2
// baseline (speedup 1.0000x reference)
#include <cuda_runtime.h>

typedef unsigned long long u64;

#define SY_CO   5202ULL        // padded per-(cls,n,co) volume: 17*17*18
#define SY_N    665856ULL      // 128 * SY_CO
#define SY_CLS  5326848ULL     // 8 * SY_N

__device__ float g_wb[6912 * 128];                    // rearranged weights
__device__ float g_y[8ULL * 8 * 128 * 17 * 17 * 18];  // class-major y (~170MB)

__constant__ int c_T[8]    = {8, 4, 4, 2, 4, 2, 2, 1};
__constant__ int c_KOFF[8] = {0, 2048, 3072, 4096, 4608, 5632, 6144, 6656};

// ---- packed f32x2 helpers (full-rate fp32 on sm_103a) ----------------------
__device__ __forceinline__ u64 dup2(float a) {
    u64 r; unsigned u = __float_as_uint(a);
    asm("mov.b64 %0, {%1, %1};" : "=l"(r) : "r"(u));
    return r;
}
__device__ __forceinline__ void ffma2(u64& d, u64 a, u64 b) {
    asm("fma.rn.f32x2 %0, %1, %2, %0;" : "+l"(d) : "l"(a), "l"(b));
}

// ---------------------------------------------------------------------------
// Weight rearrangement: g_wb[KOFF + (t*256+ci)*128 + co] = W[co][ci][jd][jh][jw]
// even dim: tap 0 -> j=0 (x at a-1), tap 1 -> j=2 (x at a); odd dim: j=1
// ---------------------------------------------------------------------------
__global__ void prep_wb(const float* __restrict__ w) {
    int cls = blockIdx.y;
    int bd = (cls >> 2) & 1, bh = (cls >> 1) & 1, bw = cls & 1;
    int nh = 2 - bh, nw = 2 - bw;
    int total = c_T[cls] * 256 * 128;
    int idx = blockIdx.x * 256 + threadIdx.x;
    if (idx >= total) return;
    int co = idx & 127;
    int ci = (idx >> 7) & 255;
    int t  = idx >> 15;
    int tw = (nw == 2) ? (t & 1) : 0;
    int tt = (nw == 2) ? (t >> 1) : t;
    int th = (nh == 2) ? (tt & 1) : 0;
    int td = (nh == 2) ? (tt >> 1) : tt;
    int jd = bd ? 1 : td * 2;
    int jh = bh ? 1 : th * 2;
    int jw = bw ? 1 : tw * 2;
    g_wb[(size_t)(c_KOFF[cls] + t * 256 + ci) * 128 + co] =
        w[(size_t)(co * 256 + ci) * 27 + jd * 9 + jh * 3 + jw];
}

// ---------------------------------------------------------------------------
// Per-class implicit GEMM: y_cls[M x 128co] = A[M x K] * B[K x 128]
// BM=128, BK=16, 256 threads, per-thread 4m x 8 co-pairs in f32x2 accumulators
// ---------------------------------------------------------------------------
__global__ __launch_bounds__(256, 2)
void gemm_cls(const float* __restrict__ x, int cls, int M) {
    const int bd = (cls >> 2) & 1, bh = (cls >> 1) & 1, bw = cls & 1;
    const int nh = 2 - bh, nw = 2 - bw;
    const int Dc = 17 - bd, Hc = 17 - bh, Wc = 17 - bw;
    const int K = 256 * c_T[cls];
    const float* __restrict__ wb = g_wb + (size_t)c_KOFF[cls] * 128;

    __shared__ float As[2][16][128];
    __shared__ float Bs[2][16][128];

    const int tid = threadIdx.x;
    const int blockM = blockIdx.x * 128;

    // A loader: one m-row per thread, 8 k's per chunk (khalf = upper/lower 8)
    const int mrow  = tid & 127;
    const int khalf = tid >> 7;
    const int m = blockM + mrow;
    const bool mval = m < M;
    int mm = mval ? m : 0;
    int aw = mm % Wc; int tq = mm / Wc;
    int ah = tq % Hc; tq /= Hc;
    int ad = tq % Dc; int an = tq / Dc;
    const float* __restrict__ xn = x + (size_t)an * (256 * 4096);

    // B loader
    const int co4 = (tid & 31) * 4;
    const int kB  = tid >> 5;   // 0..7

    u64 acc[4][8];
#pragma unroll
    for (int i = 0; i < 4; i++)
#pragma unroll
        for (int j = 0; j < 8; j++) acc[i][j] = 0ULL;

    const int nChunks = K >> 4;

    float  aR[8];
    float4 bR0, bR1;

    auto loadA = [&](int kb) {
        int k0  = kb << 4;
        int t   = k0 >> 8;                    // tap idx, constant per chunk
        int ci0 = (k0 & 255) + khalf * 8;
        int tw = (nw == 2) ? (t & 1) : 0;
        int tt = (nw == 2) ? (t >> 1) : t;
        int th = (nh == 2) ? (tt & 1) : 0;
        int td = (nh == 2) ? (tt >> 1) : tt;
        int xd = ad + (bd ? 0 : td - 1);
        int xh = ah + (bh ? 0 : th - 1);
        int xw = aw + (bw ? 0 : tw - 1);
        bool v = mval && ((unsigned)xd < 16u) && ((unsigned)xh < 16u) && ((unsigned)xw < 16u);
        const float* p = xn + (size_t)ci0 * 4096 + xd * 256 + xh * 16 + xw;
#pragma unroll
        for (int q = 0; q < 8; q++) aR[q] = v ? p[(size_t)q * 4096] : 0.f;
    };
    auto loadB = [&](int kb) {
        const float* p = wb + (size_t)(kb * 16 + kB) * 128 + co4;
        bR0 = *(const float4*)p;
        bR1 = *(const float4*)(p + 8 * 128);
    };
    auto storeS = [&](int buf) {
#pragma unroll
        for (int q = 0; q < 8; q++) As[buf][khalf * 8 + q][mrow] = aR[q];
        *(float4*)&Bs[buf][kB][co4]     = bR0;
        *(float4*)&Bs[buf][kB + 8][co4] = bR1;
    };

    loadA(0); loadB(0); storeS(0);
    __syncthreads();

    const int r = tid & 31;   // lane -> m = blockM + i*32 + r
    const int c = tid >> 5;   // warp -> co block c*16 .. c*16+15

    for (int kb = 0; kb < nChunks; ++kb) {
        int nxt = kb + 1;
        if (nxt < nChunks) { loadA(nxt); loadB(nxt); }
        int cur = kb & 1;
#pragma unroll
        for (int kk = 0; kk < 16; kk++) {
            u64 a0 = dup2(As[cur][kk][r]);
            u64 a1 = dup2(As[cur][kk][r + 32]);
            u64 a2 = dup2(As[cur][kk][r + 64]);
            u64 a3 = dup2(As[cur][kk][r + 96]);
            const u64* bp = (const u64*)&Bs[cur][kk][c * 16];  // broadcast
#pragma unroll
            for (int j = 0; j < 8; j++) {
                u64 bv = bp[j];
                ffma2(acc[0][j], a0, bv);
                ffma2(acc[1][j], a1, bv);
                ffma2(acc[2][j], a2, bv);
                ffma2(acc[3][j], a3, bv);
            }
        }
        if (nxt < nChunks) storeS(nxt & 1);
        __syncthreads();
    }

    // epilogue: scatter into class-major y (coalesced along w per lane group)
#pragma unroll
    for (int i = 0; i < 4; i++) {
        int mi = blockM + i * 32 + r;
        if (mi < M) {
            int w_ = mi % Wc; int tq2 = mi / Wc;
            int h_ = tq2 % Hc; tq2 /= Hc;
            int d_ = tq2 % Dc; int n_ = tq2 / Dc;
            float* yp = g_y + (size_t)cls * SY_CLS + (size_t)n_ * SY_N
                      + (size_t)(c * 16) * SY_CO + d_ * 306 + h_ * 18 + w_;
#pragma unroll
            for (int j = 0; j < 8; j++) {
                u64 v = acc[i][j];
                yp[0]     = __uint_as_float((unsigned)v);
                yp[SY_CO] = __uint_as_float((unsigned)(v >> 32));
                yp += 2 * SY_CO;
            }
        }
    }
}

// ---------------------------------------------------------------------------
// FIR ([0.25,0.75,0.75,0.25] separable) + interleave + bias.
// Block = one (n, co); 1024 threads = 32x32 (zh, zw); rolling d-window.
// Global p-coord q in [0,33): y[q] = y_cls[(q&1)...][q>>1]; outside -> 0.
// ---------------------------------------------------------------------------
__global__ __launch_bounds__(1024)
void fir_kernel(const float* __restrict__ bias, float* __restrict__ out) {
    __shared__ float buf[2][33][36];

    const int blk = blockIdx.x;
    const int n = blk >> 7, co = blk & 127;
    const int tid = threadIdx.x;
    const int zh = tid >> 5, zw = tid & 31;

    const float* __restrict__ ybase = g_y + (size_t)n * SY_N + (size_t)co * SY_CO;
    const float bv = bias[co];
    float* __restrict__ op = out + (size_t)blk * 32768;

    const float C0 = 0.25f, C1 = 0.75f;
    float s0 = 0.f, s1 = 0.f, s2 = 0.f, s3 = 0.f;

    for (int pd = 0; pd < 35; ++pd) {
        if (pd <= 32) {
            int pbit = pd & 1, ad = pd >> 1;
            for (int e = tid; e < 1089; e += 1024) {
                int ph = e / 33, pw = e - ph * 33;
                int cls = (pbit << 2) | ((ph & 1) << 1) | (pw & 1);
                buf[pd & 1][ph][pw] =
                    ybase[(size_t)cls * SY_CLS + ad * 306 + (ph >> 1) * 18 + (pw >> 1)];
            }
        }
        __syncthreads();

        float snew = 0.f;
        if (pd <= 32) {
            const float cw[4] = {C0, C1, C1, C0};
#pragma unroll
            for (int mh = 0; mh < 4; mh++) {
                int ph = zh - 1 + mh;
                if ((unsigned)ph < 33u) {
                    float rs = 0.f;
#pragma unroll
                    for (int mw = 0; mw < 4; mw++) {
                        int pw = zw - 1 + mw;
                        if ((unsigned)pw < 33u) rs += cw[mw] * buf[pd & 1][ph][pw];
                    }
                    snew += cw[mh] * rs;
                }
            }
        }
        s0 = s1; s1 = s2; s2 = s3; s3 = snew;

        if (pd >= 2 && pd <= 33) {
            int zd = pd - 2;
            float z = C0 * (s0 + s3) + C1 * (s1 + s2) + bv;
            op[(size_t)zd * 1024 + zh * 32 + zw] = z;
        }
    }
}

extern "C" void kernel_launch(void* const* d_in, const int* in_sizes, int n_in,
                              void* d_out, int out_size) {
    const float* x    = (const float*)d_in[0];
    const float* w    = (const float*)d_in[1];
    const float* bias = (const float*)d_in[2];
    float* out = (float*)d_out;

    prep_wb<<<dim3(1024, 8), 256>>>(w);

    static const int Ms[8] = {39304, 36992, 36992, 34816, 36992, 34816, 34816, 32768};
    for (int cls = 0; cls < 8; ++cls) {
        int M = Ms[cls];
        gemm_cls<<<(M + 127) / 128, 256>>>(x, cls, M);
    }

    fir_kernel<<<1024, 1024>>>(bias, out);
}

// round 4
// speedup vs baseline: 1.8541x; 1.8541x over previous
#include <cuda_runtime.h>
#include <cuda_bf16.h>
#include <cstdint>

typedef unsigned int u32;
typedef unsigned short u16;

// ---------------------------------------------------------------------------
// Scratch
// ---------------------------------------------------------------------------
__device__ __align__(16) u16 g_Ah[8388608];            // bf16 hi of x, ci-packed
__device__ __align__(16) u16 g_Al[8388608];            // bf16 lo of x
__device__ __align__(16) unsigned char g_B[432 * 8192]; // per-chunk swizzled [Bh|Bl]
__device__ float g_y[40144896];                         // y[n][co][33][33][36]

// per-class tables
__constant__ int c_cumB[9] = {0, 308, 597, 886, 1158, 1447, 1719, 1991, 2247};
__constant__ int c_cumK[9] = {0, 2048, 3072, 4096, 4608, 5632, 6144, 6656, 6912};

// ---------------------------------------------------------------------------
// smem swizzle: tile rows of 32B (16 bf16), 16B units; classic sm80 XOR
// ---------------------------------------------------------------------------
__device__ __forceinline__ u32 sw_off(u32 r, u32 u) {
    u32 line = r >> 2;
    return line * 128 + ((((r & 3) * 2 + u) ^ (line & 7)) << 4);
}
__device__ __forceinline__ u32 smem_u32(const void* p) {
    u32 a;
    asm("{ .reg .u64 t; cvta.to.shared.u64 t, %1; cvt.u32.u64 %0, t; }" : "=r"(a) : "l"(p));
    return a;
}
__device__ __forceinline__ void ldm4(u32 addr, u32& r0, u32& r1, u32& r2, u32& r3) {
    asm volatile("ldmatrix.sync.aligned.m8n8.x4.shared.b16 {%0,%1,%2,%3}, [%4];"
                 : "=r"(r0), "=r"(r1), "=r"(r2), "=r"(r3) : "r"(addr));
}
__device__ __forceinline__ void mma16816(float* c, u32 a0, u32 a1, u32 a2, u32 a3,
                                         u32 b0, u32 b1) {
    asm volatile("mma.sync.aligned.m16n8k16.row.col.f32.bf16.bf16.f32 "
                 "{%0,%1,%2,%3},{%4,%5,%6,%7},{%8,%9},{%0,%1,%2,%3};"
                 : "+f"(c[0]), "+f"(c[1]), "+f"(c[2]), "+f"(c[3])
                 : "r"(a0), "r"(a1), "r"(a2), "r"(a3), "r"(b0), "r"(b1));
}

// ---------------------------------------------------------------------------
// prep_x: split x to bf16 h/l, layout (((ci>>3)*8 + n)*4096 + s)*8 + (ci&7)
// so 8 consecutive ci for fixed (n,s) are 16B contiguous.
// ---------------------------------------------------------------------------
__global__ void prep_x(const float* __restrict__ x) {
    int idx = blockIdx.x * 1024 + threadIdx.x;   // 8,388,608 total
    int n = idx >> 20, ci = (idx >> 12) & 255, s = idx & 4095;
    float v = x[idx];
    __nv_bfloat16 h = __float2bfloat16(v);
    __nv_bfloat16 l = __float2bfloat16(v - __bfloat162float(h));
    size_t o = ((size_t)((ci >> 3) * 8 + n)) * 32768 + (size_t)s * 8 + (ci & 7);
    g_Ah[o] = __bfloat16_as_ushort(h);
    g_Al[o] = __bfloat16_as_ushort(l);
}

// ---------------------------------------------------------------------------
// prep_w: per global k (class/tap/ci) and co, write swizzled chunk images.
// Chunk image (8KB): [Bh 4KB | Bl 4KB], rows = co, 16 k-cols, XOR swizzle.
// ---------------------------------------------------------------------------
__global__ void prep_w(const float* __restrict__ w) {
    int idx = blockIdx.x * 256 + threadIdx.x;    // 884,736 total
    int co = idx & 127;
    int gk = idx >> 7;
    int cls = 0;
    while (gk >= c_cumK[cls + 1]) cls++;
    int lk = gk - c_cumK[cls];
    int t = lk >> 8, ci = lk & 255;
    int bd = (cls >> 2) & 1, bh = (cls >> 1) & 1, bw = cls & 1;
    int nh = 2 - bh, nw = 2 - bw;
    int tw = (nw == 2) ? (t & 1) : 0;
    int tt = (nw == 2) ? (t >> 1) : t;
    int th = (nh == 2) ? (tt & 1) : 0;
    int td = (nh == 2) ? (tt >> 1) : tt;
    int jd = bd ? 1 : td * 2;
    int jh = bh ? 1 : th * 2;
    int jw = bw ? 1 : tw * 2;
    float v = w[(size_t)(co * 256 + ci) * 27 + jd * 9 + jh * 3 + jw];
    __nv_bfloat16 h = __float2bfloat16(v);
    __nv_bfloat16 l = __float2bfloat16(v - __bfloat162float(h));
    int chunk = (c_cumK[cls] >> 4) + (lk >> 4);
    int kk = lk & 15;
    u32 so = sw_off((u32)co, (u32)(kk >> 3)) + (kk & 7) * 2;
    unsigned char* base = g_B + (size_t)chunk * 8192;
    *(u16*)(base + so)        = __bfloat16_as_ushort(h);
    *(u16*)(base + 4096 + so) = __bfloat16_as_ushort(l);
}

// ---------------------------------------------------------------------------
// gemm_hmma: merged all-class HMMA GEMM. BM=128, BN=128, BK=16(fp32-k),
// 256 threads (8 warps, 2m x 4n, warp 64x32). 3-term bf16 per chunk.
// Epilogue: dense y[n][co][pd][ph][pw] (pw pad 36).
// ---------------------------------------------------------------------------
__global__ void __launch_bounds__(256, 1) gemm_hmma() {
    __shared__ uint4 smem4[2048];      // 32KB: 2 bufs x {Ah,Al,Bh,Bl} x 4KB
    unsigned char* sm = (unsigned char*)smem4;
    const u32 smb = smem_u32(sm);

    const int bid = blockIdx.x;
    int cls = 0;
    while (bid >= c_cumB[cls + 1]) cls++;
    const int mtile = bid - c_cumB[cls];
    const int bd = (cls >> 2) & 1, bh = (cls >> 1) & 1, bw = cls & 1;
    const int nh = 2 - bh, nw = 2 - bw;
    const int Dc = 17 - bd, Hc = 17 - bh, Wc = 17 - bw;
    const int M = 8 * Dc * Hc * Wc;
    const int nCh = (c_cumK[cls + 1] - c_cumK[cls]) >> 4;
    const int chBase = c_cumK[cls] >> 4;
    const int blockM = mtile * 128;

    const int tid = threadIdx.x;
    const int mrow = tid & 127, khalf = tid >> 7;
    const int m = blockM + mrow;
    const bool mval = m < M;
    int mm = mval ? m : 0;
    int aw = mm % Wc; int tq = mm / Wc;
    int ah = tq % Hc; tq /= Hc;
    int ad = tq % Dc; int an = tq / Dc;

    // loader staging regs
    uint4 aH4, aL4, bv0, bv1;
    const u32 stsoff = sw_off((u32)mrow, (u32)khalf);

    auto loadRegs = [&](int kb) {
        int t = kb >> 4;
        int cp = (kb & 15) * 2 + khalf;        // ci-pack (8 ci)
        int tw = (nw == 2) ? (t & 1) : 0;
        int tt = (nw == 2) ? (t >> 1) : t;
        int th = (nh == 2) ? (tt & 1) : 0;
        int td = (nh == 2) ? (tt >> 1) : tt;
        int xd = ad + (bd ? 0 : td - 1);
        int xh = ah + (bh ? 0 : th - 1);
        int xw = aw + (bw ? 0 : tw - 1);
        bool v = mval && ((unsigned)xd < 16u) && ((unsigned)xh < 16u) && ((unsigned)xw < 16u);
        size_t o = ((size_t)(cp * 8 + an)) * 32768 + (size_t)(xd * 256 + xh * 16 + xw) * 8;
        if (v) {
            aH4 = *(const uint4*)(g_Ah + o);
            aL4 = *(const uint4*)(g_Al + o);
        } else {
            aH4 = make_uint4(0, 0, 0, 0);
            aL4 = make_uint4(0, 0, 0, 0);
        }
        const uint4* gb = (const uint4*)(g_B + (size_t)(chBase + kb) * 8192);
        bv0 = gb[tid];
        bv1 = gb[tid + 256];
    };
    auto stsRegs = [&](int buf) {
        u32 o = (u32)buf * 16384;
        *(uint4*)(sm + o + stsoff)        = aH4;
        *(uint4*)(sm + o + 4096 + stsoff) = aL4;
        ((uint4*)(sm + o + 8192))[tid]       = bv0;
        ((uint4*)(sm + o + 8192))[tid + 256] = bv1;
    };

    const int lane = tid & 31, wid = tid >> 5;
    const int wM = (wid >> 2) * 64, wN = (wid & 3) * 32;
    const u32 arow = lane & 15, au = lane >> 4;
    const u32 brow = ((lane >> 4) << 3) + (lane & 7), bu = (lane >> 3) & 1;

    float acc[4][4][4];
#pragma unroll
    for (int t = 0; t < 4; t++)
#pragma unroll
        for (int j = 0; j < 4; j++)
#pragma unroll
            for (int q = 0; q < 4; q++) acc[t][j][q] = 0.f;

    auto pass = [&](u32 af[4][4], u32 bf2[2][4]) {
#pragma unroll
        for (int t = 0; t < 4; t++)
#pragma unroll
            for (int j = 0; j < 4; j++)
                mma16816(acc[t][j], af[t][0], af[t][1], af[t][2], af[t][3],
                         bf2[j >> 1][(j & 1) * 2], bf2[j >> 1][(j & 1) * 2 + 1]);
    };

    auto computeChunk = [&](int buf) {
        const u32 ob = smb + (u32)buf * 16384;
        u32 af[4][4], bf2[2][4];
#pragma unroll
        for (int t = 0; t < 4; t++)
            ldm4(ob + sw_off(wM + t * 16 + arow, au), af[t][0], af[t][1], af[t][2], af[t][3]);
#pragma unroll
        for (int s = 0; s < 2; s++)
            ldm4(ob + 8192 + sw_off(wN + s * 16 + brow, bu), bf2[s][0], bf2[s][1], bf2[s][2], bf2[s][3]);
        pass(af, bf2);                                  // Ah * Bh
#pragma unroll
        for (int s = 0; s < 2; s++)
            ldm4(ob + 12288 + sw_off(wN + s * 16 + brow, bu), bf2[s][0], bf2[s][1], bf2[s][2], bf2[s][3]);
        pass(af, bf2);                                  // Ah * Bl
#pragma unroll
        for (int t = 0; t < 4; t++)
            ldm4(ob + 4096 + sw_off(wM + t * 16 + arow, au), af[t][0], af[t][1], af[t][2], af[t][3]);
#pragma unroll
        for (int s = 0; s < 2; s++)
            ldm4(ob + 8192 + sw_off(wN + s * 16 + brow, bu), bf2[s][0], bf2[s][1], bf2[s][2], bf2[s][3]);
        pass(af, bf2);                                  // Al * Bh
    };

    loadRegs(0); stsRegs(0);
    __syncthreads();
    for (int kb = 0; kb < nCh; kb++) {
        if (kb + 1 < nCh) loadRegs(kb + 1);
        computeChunk(kb & 1);
        if (kb + 1 < nCh) stsRegs((kb + 1) & 1);
        __syncthreads();
    }

    // epilogue -> dense y
    const int g = lane >> 2, tq4 = lane & 3;
#pragma unroll
    for (int t = 0; t < 4; t++) {
#pragma unroll
        for (int half = 0; half < 2; half++) {
            int mi = blockM + wM + t * 16 + g + half * 8;
            if (mi < M) {
                int w_ = mi % Wc; int q = mi / Wc;
                int h_ = q % Hc; q /= Hc;
                int d_ = q % Dc; int nb = q / Dc;
                int pd = 2 * d_ + bd, ph = 2 * h_ + bh, pw = 2 * w_ + bw;
                size_t base = (size_t)nb * 5018112 + (size_t)pd * 1188 + ph * 36 + pw;
                int co0 = wN + tq4 * 2;
#pragma unroll
                for (int j = 0; j < 4; j++) {
                    size_t off = base + (size_t)(co0 + j * 8) * 39204;
                    g_y[off]         = acc[t][j][half * 2];
                    g_y[off + 39204] = acc[t][j][half * 2 + 1];
                }
            }
        }
    }
}

// ---------------------------------------------------------------------------
// fir_kernel: FIR [0.25,0.75,0.75,0.25]^3 + bias on dense y, rolling d-window
// ---------------------------------------------------------------------------
__global__ __launch_bounds__(1024) void fir_kernel(const float* __restrict__ bias,
                                                   float* __restrict__ out) {
    __shared__ float buf[2][33][36];

    const int blk = blockIdx.x;
    const int n = blk >> 7, co = blk & 127;
    const int tid = threadIdx.x;
    const int zh = tid >> 5, zw = tid & 31;

    const float* __restrict__ ybase = g_y + (size_t)(n * 128 + co) * 39204;
    const float bv = bias[co];
    float* __restrict__ op = out + (size_t)blk * 32768;

    const float C0 = 0.25f, C1 = 0.75f;
    float s0 = 0.f, s1 = 0.f, s2 = 0.f, s3 = 0.f;

    for (int pd = 0; pd < 35; ++pd) {
        if (pd <= 32) {
            const float* pl = ybase + (size_t)pd * 1188;
            float* bf = &buf[pd & 1][0][0];
            for (int e = tid; e < 1188; e += 1024) bf[e] = pl[e];
        }
        __syncthreads();

        float snew = 0.f;
        if (pd <= 32) {
            const float cw[4] = {C0, C1, C1, C0};
#pragma unroll
            for (int mh = 0; mh < 4; mh++) {
                int ph = zh - 1 + mh;
                if ((unsigned)ph < 33u) {
                    float rs = 0.f;
#pragma unroll
                    for (int mw = 0; mw < 4; mw++) {
                        int pw = zw - 1 + mw;
                        if ((unsigned)pw < 33u) rs += cw[mw] * buf[pd & 1][ph][pw];
                    }
                    snew += cw[mh] * rs;
                }
            }
        }
        s0 = s1; s1 = s2; s2 = s3; s3 = snew;

        if (pd >= 2 && pd <= 33) {
            int zd = pd - 2;
            float z = C0 * (s0 + s3) + C1 * (s1 + s2) + bv;
            op[(size_t)zd * 1024 + zh * 32 + zw] = z;
        }
    }
}

// ---------------------------------------------------------------------------
extern "C" void kernel_launch(void* const* d_in, const int* in_sizes, int n_in,
                              void* d_out, int out_size) {
    const float* x    = (const float*)d_in[0];
    const float* w    = (const float*)d_in[1];
    const float* bias = (const float*)d_in[2];
    float* out = (float*)d_out;

    prep_x<<<8192, 1024>>>(x);
    prep_w<<<3456, 256>>>(w);
    gemm_hmma<<<2247, 256>>>();
    fir_kernel<<<1024, 1024>>>(bias, out);
}

// round 9
// speedup vs baseline: 2.1283x; 1.1479x over previous
#include <cuda_runtime.h>
#include <cuda_bf16.h>
#include <cstdint>

typedef unsigned int u32;
typedef unsigned short u16;

// ---------------------------------------------------------------------------
// Scratch
// ---------------------------------------------------------------------------
__device__ __align__(16) u16 g_Ah[8388608];             // bf16 hi of x, ci-packed
__device__ __align__(16) u16 g_Al[8388608];             // bf16 lo of x
__device__ __align__(16) unsigned char g_B[432 * 8192]; // per-chunk swizzled [Bh|Bl]
__device__ float g_y[40144896];                          // y[n][co][33][33][36]

__constant__ int c_cumB[9] = {0, 308, 597, 886, 1158, 1447, 1719, 1991, 2247};
__constant__ int c_cumK[9] = {0, 2048, 3072, 4096, 4608, 5632, 6144, 6656, 6912};

// ---------------------------------------------------------------------------
// helpers
// ---------------------------------------------------------------------------
__device__ __forceinline__ u32 sw_off(u32 r, u32 u) {
    u32 line = r >> 2;
    return line * 128 + ((((r & 3) * 2 + u) ^ (line & 7)) << 4);
}
__device__ __forceinline__ u32 smem_u32(const void* p) {
    u32 a;
    asm("{ .reg .u64 t; cvta.to.shared.u64 t, %1; cvt.u32.u64 %0, t; }" : "=r"(a) : "l"(p));
    return a;
}
__device__ __forceinline__ void ldm4(u32 addr, u32& r0, u32& r1, u32& r2, u32& r3) {
    asm volatile("ldmatrix.sync.aligned.m8n8.x4.shared.b16 {%0,%1,%2,%3}, [%4];"
                 : "=r"(r0), "=r"(r1), "=r"(r2), "=r"(r3) : "r"(addr));
}
__device__ __forceinline__ void mma16816(float* c, u32 a0, u32 a1, u32 a2, u32 a3,
                                         u32 b0, u32 b1) {
    asm volatile("mma.sync.aligned.m16n8k16.row.col.f32.bf16.bf16.f32 "
                 "{%0,%1,%2,%3},{%4,%5,%6,%7},{%8,%9},{%0,%1,%2,%3};"
                 : "+f"(c[0]), "+f"(c[1]), "+f"(c[2]), "+f"(c[3])
                 : "r"(a0), "r"(a1), "r"(a2), "r"(a3), "r"(b0), "r"(b1));
}
__device__ __forceinline__ void cpa16(u32 dst, const void* src, u32 sz) {
    asm volatile("cp.async.cg.shared.global [%0], [%1], 16, %2;"
                 :: "r"(dst), "l"(src), "r"(sz) : "memory");
}
#define CP_COMMIT() asm volatile("cp.async.commit_group;" ::: "memory")
#define CP_WAIT2()  asm volatile("cp.async.wait_group 2;" ::: "memory")

// ---------------------------------------------------------------------------
// prep_x: split x into bf16 hi/lo, ci-packed: (((ci>>3)*8+n)*4096+s)*8+(ci&7)
// ---------------------------------------------------------------------------
__global__ void prep_x(const float* __restrict__ x) {
    int idx = blockIdx.x * 256 + threadIdx.x;   // 2,097,152 threads x 4 elems
    int base = idx * 4;
    int n = base >> 20, ci = (base >> 12) & 255, s = base & 4095;
    float4 v4 = *(const float4*)(x + base);
    size_t o = ((size_t)((ci >> 3) * 8 + n)) * 32768 + (size_t)s * 8 + (ci & 7);
    float vs[4] = {v4.x, v4.y, v4.z, v4.w};
#pragma unroll
    for (int q = 0; q < 4; q++) {
        float v = vs[q];
        __nv_bfloat16 h = __float2bfloat16(v);
        __nv_bfloat16 l = __float2bfloat16(v - __bfloat162float(h));
        g_Ah[o + q * 8] = __bfloat16_as_ushort(h);
        g_Al[o + q * 8] = __bfloat16_as_ushort(l);
    }
}

// ---------------------------------------------------------------------------
// prep_w: swizzled per-chunk B images: [Bh 4KB | Bl 4KB]
// ---------------------------------------------------------------------------
__global__ void prep_w(const float* __restrict__ w) {
    int idx = blockIdx.x * 256 + threadIdx.x;    // 884,736 total
    int co = idx & 127;
    int gk = idx >> 7;
    int cls = 0;
    while (gk >= c_cumK[cls + 1]) cls++;
    int lk = gk - c_cumK[cls];
    int t = lk >> 8, ci = lk & 255;
    int bd = (cls >> 2) & 1, bh = (cls >> 1) & 1, bw = cls & 1;
    int nh = 2 - bh, nw = 2 - bw;
    int tw = (nw == 2) ? (t & 1) : 0;
    int tt = (nw == 2) ? (t >> 1) : t;
    int th = (nh == 2) ? (tt & 1) : 0;
    int td = (nh == 2) ? (tt >> 1) : tt;
    int jd = bd ? 1 : td * 2;
    int jh = bh ? 1 : th * 2;
    int jw = bw ? 1 : tw * 2;
    float v = w[(size_t)(co * 256 + ci) * 27 + jd * 9 + jh * 3 + jw];
    __nv_bfloat16 h = __float2bfloat16(v);
    __nv_bfloat16 l = __float2bfloat16(v - __bfloat162float(h));
    int chunk = (c_cumK[cls] >> 4) + (lk >> 4);
    int kk = lk & 15;
    u32 so = sw_off((u32)co, (u32)(kk >> 3)) + (kk & 7) * 2;
    unsigned char* base = g_B + (size_t)chunk * 8192;
    *(u16*)(base + so)        = __bfloat16_as_ushort(h);
    *(u16*)(base + 4096 + so) = __bfloat16_as_ushort(l);
}

// ---------------------------------------------------------------------------
// gemm_hmma: merged all-class HMMA GEMM, 4-stage cp.async pipeline.
// BM=128, BN=128, BK=16 fp32-k (3 bf16 terms), 8 warps (2m x 4n, warp 64x32).
// Stage = 16KB: [Ah 4K | Al 4K | Bh 4K | Bl 4K].
// ---------------------------------------------------------------------------
#define NSTAGE 4
#define STG 16384
#define GEMM_SMEM (NSTAGE * STG)

__global__ void __launch_bounds__(256, 2) gemm_hmma() {
    extern __shared__ unsigned char sm[];
    const u32 smb = smem_u32(sm);

    const int bid = blockIdx.x;
    int cls = 0;
    while (bid >= c_cumB[cls + 1]) cls++;
    const int mtile = bid - c_cumB[cls];
    const int bd = (cls >> 2) & 1, bh = (cls >> 1) & 1, bw = cls & 1;
    const int nh = 2 - bh, nw = 2 - bw;
    const int Dc = 17 - bd, Hc = 17 - bh, Wc = 17 - bw;
    const int M = 8 * Dc * Hc * Wc;
    const int nCh = (c_cumK[cls + 1] - c_cumK[cls]) >> 4;
    const int chBase = c_cumK[cls] >> 4;
    const int blockM = mtile * 128;

    const int tid = threadIdx.x;
    const int mrow = tid & 127, khalf = tid >> 7;
    const int m = blockM + mrow;
    const bool mval = m < M;
    int mm = mval ? m : 0;
    int aw = mm % Wc; int tq = mm / Wc;
    int ah = tq % Hc; tq /= Hc;
    int ad = tq % Dc; int an = tq / Dc;

    const u32 stsA = sw_off((u32)mrow, (u32)khalf);
    const u32 stsB = (u32)tid * 16;

    auto issueStage = [&](int kb) {
        const u32 base = smb + (u32)(kb & 3) * STG;
        int t = kb >> 4;
        int tw = (nw == 2) ? (t & 1) : 0;
        int tt = (nw == 2) ? (t >> 1) : t;
        int th = (nh == 2) ? (tt & 1) : 0;
        int td = (nh == 2) ? (tt >> 1) : tt;
        int xd = ad + (bd ? 0 : td - 1);
        int xh = ah + (bh ? 0 : th - 1);
        int xw = aw + (bw ? 0 : tw - 1);
        bool v = mval && ((unsigned)xd < 16u) && ((unsigned)xh < 16u) && ((unsigned)xw < 16u);
        size_t o = ((size_t)(((kb & 15) * 2 + khalf) * 8 + an)) * 32768
                 + (size_t)(xd * 256 + xh * 16 + xw) * 8;
        u32 sz = v ? 16u : 0u;
        cpa16(base + stsA,        g_Ah + o, sz);
        cpa16(base + 4096 + stsA, g_Al + o, sz);
        const unsigned char* gb = g_B + (size_t)(chBase + kb) * 8192 + tid * 16;
        cpa16(base + 8192  + stsB, gb, 16);
        cpa16(base + 12288 + stsB, gb + 4096, 16);
        CP_COMMIT();
    };

    const int lane = tid & 31, wid = tid >> 5;
    const int wM = (wid >> 2) * 64, wN = (wid & 3) * 32;
    const u32 arow = lane & 15, au = lane >> 4;
    const u32 brow = ((lane >> 4) << 3) + (lane & 7), bu = (lane >> 3) & 1;

    float acc[4][4][4];
#pragma unroll
    for (int t = 0; t < 4; t++)
#pragma unroll
        for (int j = 0; j < 4; j++)
#pragma unroll
            for (int q = 0; q < 4; q++) acc[t][j][q] = 0.f;

    auto pass = [&](u32 af[4][4], u32 bf2[2][4]) {
#pragma unroll
        for (int t = 0; t < 4; t++)
#pragma unroll
            for (int j = 0; j < 4; j++)
                mma16816(acc[t][j], af[t][0], af[t][1], af[t][2], af[t][3],
                         bf2[j >> 1][(j & 1) * 2], bf2[j >> 1][(j & 1) * 2 + 1]);
    };

    auto computeChunk = [&](int buf) {
        const u32 ob = smb + (u32)buf * STG;
        u32 af[4][4], bhf[2][4], blf[2][4];
#pragma unroll
        for (int t = 0; t < 4; t++)
            ldm4(ob + sw_off(wM + t * 16 + arow, au), af[t][0], af[t][1], af[t][2], af[t][3]);
#pragma unroll
        for (int s = 0; s < 2; s++)
            ldm4(ob + 8192 + sw_off(wN + s * 16 + brow, bu), bhf[s][0], bhf[s][1], bhf[s][2], bhf[s][3]);
#pragma unroll
        for (int s = 0; s < 2; s++)
            ldm4(ob + 12288 + sw_off(wN + s * 16 + brow, bu), blf[s][0], blf[s][1], blf[s][2], blf[s][3]);
        pass(af, bhf);                                 // Ah * Bh
        pass(af, blf);                                 // Ah * Bl
#pragma unroll
        for (int t = 0; t < 4; t++)
            ldm4(ob + 4096 + sw_off(wM + t * 16 + arow, au), af[t][0], af[t][1], af[t][2], af[t][3]);
        pass(af, bhf);                                 // Al * Bh
    };

    issueStage(0); issueStage(1); issueStage(2);
    for (int kb = 0; kb < nCh; kb++) {
        CP_WAIT2();
        __syncthreads();
        if (kb + NSTAGE - 1 < nCh) issueStage(kb + NSTAGE - 1);
        else CP_COMMIT();
        computeChunk(kb & 3);
    }

    // epilogue -> dense y[n][co][pd][ph][pw36]
    const int g = lane >> 2, tq4 = lane & 3;
#pragma unroll
    for (int t = 0; t < 4; t++) {
#pragma unroll
        for (int half = 0; half < 2; half++) {
            int mi = blockM + wM + t * 16 + g + half * 8;
            if (mi < M) {
                int w_ = mi % Wc; int q = mi / Wc;
                int h_ = q % Hc; q /= Hc;
                int d_ = q % Dc; int nb = q / Dc;
                int pd = 2 * d_ + bd, ph = 2 * h_ + bh, pw = 2 * w_ + bw;
                size_t base = (size_t)nb * 5018112 + (size_t)pd * 1188 + ph * 36 + pw;
                int co0 = wN + tq4 * 2;
#pragma unroll
                for (int j = 0; j < 4; j++) {
                    size_t off = base + (size_t)(co0 + j * 8) * 39204;
                    g_y[off]         = acc[t][j][half * 2];
                    g_y[off + 39204] = acc[t][j][half * 2 + 1];
                }
            }
        }
    }
}

// ---------------------------------------------------------------------------
// fir_kernel: separable FIR [0.25,0.75,0.75,0.25]^3 + bias, rolling d-ring.
// Per plane: row-pass into tmp, then column-pass from tmp.
// ---------------------------------------------------------------------------
__global__ __launch_bounds__(1024) void fir_kernel(const float* __restrict__ bias,
                                                   float* __restrict__ out) {
    __shared__ float plane[33][36];
    __shared__ float tmp[33][33];

    const int blk = blockIdx.x;
    const int n = blk >> 7, co = blk & 127;
    const int tid = threadIdx.x;
    const int zh = tid >> 5, zw = tid & 31;

    const float* __restrict__ ybase = g_y + (size_t)(n * 128 + co) * 39204;
    const float bv = bias[co];
    float* __restrict__ op = out + (size_t)blk * 32768;

    const float C0 = 0.25f, C1 = 0.75f;
    const float cw[4] = {C0, C1, C1, C0};
    float s0 = 0.f, s1 = 0.f, s2 = 0.f, s3 = 0.f;

    for (int pd = 0; pd < 35; ++pd) {
        if (pd <= 32) {
            const float* pl = ybase + (size_t)pd * 1188;
            float* bf = &plane[0][0];
            for (int e = tid; e < 1188; e += 1024) bf[e] = pl[e];
        }
        __syncthreads();

        if (pd <= 32) {
            for (int e = tid; e < 1056; e += 1024) {    // 33 rows x 32 zw
                int ph = e >> 5, zww = e & 31;
                float rs = 0.f;
#pragma unroll
                for (int mw = 0; mw < 4; mw++) {
                    int pw = zww - 1 + mw;
                    if ((unsigned)pw < 33u) rs += cw[mw] * plane[ph][pw];
                }
                tmp[ph][zww] = rs;
            }
        }
        __syncthreads();

        float snew = 0.f;
        if (pd <= 32) {
#pragma unroll
            for (int mh = 0; mh < 4; mh++) {
                int ph = zh - 1 + mh;
                if ((unsigned)ph < 33u) snew += cw[mh] * tmp[ph][zw];
            }
        }
        s0 = s1; s1 = s2; s2 = s3; s3 = snew;

        if (pd >= 2 && pd <= 33) {
            int zd = pd - 2;
            float z = C0 * (s0 + s3) + C1 * (s1 + s2) + bv;
            op[(size_t)zd * 1024 + zh * 32 + zw] = z;
        }
    }
}

// ---------------------------------------------------------------------------
extern "C" void kernel_launch(void* const* d_in, const int* in_sizes, int n_in,
                              void* d_out, int out_size) {
    const float* x    = (const float*)d_in[0];
    const float* w    = (const float*)d_in[1];
    const float* bias = (const float*)d_in[2];
    float* out = (float*)d_out;

    cudaFuncSetAttribute(gemm_hmma, cudaFuncAttributeMaxDynamicSharedMemorySize, GEMM_SMEM);

    prep_x<<<8192, 256>>>(x);
    prep_w<<<3456, 256>>>(w);
    gemm_hmma<<<2247, 256, GEMM_SMEM>>>();
    fir_kernel<<<1024, 1024>>>(bias, out);
}

// round 13
// speedup vs baseline: 2.4573x; 1.1546x over previous
#include <cuda_runtime.h>
#include <cuda_bf16.h>
#include <cstdint>

typedef unsigned int u32;
typedef unsigned short u16;

// ---------------------------------------------------------------------------
// Scratch
// ---------------------------------------------------------------------------
__device__ __align__(16) u16 g_Ah[8388608];             // bf16 hi of x, ci-packed
__device__ __align__(16) u16 g_Al[8388608];             // bf16 lo of x
__device__ __align__(16) unsigned char g_B[432 * 8192]; // per-chunk swizzled [Bh|Bl]
__device__ float g_y[40144896];                          // y[n][co][33][33][18ev|18od]

__constant__ int c_cumB[9] = {0, 308, 597, 886, 1158, 1447, 1719, 1991, 2247};
__constant__ int c_cumK[9] = {0, 2048, 3072, 4096, 4608, 5632, 6144, 6656, 6912};

// ---------------------------------------------------------------------------
// helpers
// ---------------------------------------------------------------------------
__device__ __forceinline__ u32 sw_off(u32 r, u32 u) {
    u32 line = r >> 2;
    return line * 128 + ((((r & 3) * 2 + u) ^ (line & 7)) << 4);
}
__device__ __forceinline__ u32 smem_u32(const void* p) {
    u32 a;
    asm("{ .reg .u64 t; cvta.to.shared.u64 t, %1; cvt.u32.u64 %0, t; }" : "=r"(a) : "l"(p));
    return a;
}
__device__ __forceinline__ void ldm4(u32 addr, u32& r0, u32& r1, u32& r2, u32& r3) {
    asm volatile("ldmatrix.sync.aligned.m8n8.x4.shared.b16 {%0,%1,%2,%3}, [%4];"
                 : "=r"(r0), "=r"(r1), "=r"(r2), "=r"(r3) : "r"(addr));
}
__device__ __forceinline__ void mma16816(float* c, u32 a0, u32 a1, u32 a2, u32 a3,
                                         u32 b0, u32 b1) {
    asm volatile("mma.sync.aligned.m16n8k16.row.col.f32.bf16.bf16.f32 "
                 "{%0,%1,%2,%3},{%4,%5,%6,%7},{%8,%9},{%0,%1,%2,%3};"
                 : "+f"(c[0]), "+f"(c[1]), "+f"(c[2]), "+f"(c[3])
                 : "r"(a0), "r"(a1), "r"(a2), "r"(a3), "r"(b0), "r"(b1));
}
__device__ __forceinline__ void cpa16(u32 dst, const void* src, u32 sz) {
    asm volatile("cp.async.cg.shared.global [%0], [%1], 16, %2;"
                 :: "r"(dst), "l"(src), "r"(sz) : "memory");
}
#define CP_COMMIT() asm volatile("cp.async.commit_group;" ::: "memory")
#define CP_WAIT2()  asm volatile("cp.async.wait_group 2;" ::: "memory")

// ---------------------------------------------------------------------------
// prep_x: split x into bf16 hi/lo, ci-packed: (((ci>>3)*8+n)*4096+s)*8+(ci&7)
// ---------------------------------------------------------------------------
__global__ void prep_x(const float* __restrict__ x) {
    int idx = blockIdx.x * 256 + threadIdx.x;
    int base = idx * 4;
    int n = base >> 20, ci = (base >> 12) & 255, s = base & 4095;
    float4 v4 = *(const float4*)(x + base);
    size_t o = ((size_t)((ci >> 3) * 8 + n)) * 32768 + (size_t)s * 8 + (ci & 7);
    float vs[4] = {v4.x, v4.y, v4.z, v4.w};
#pragma unroll
    for (int q = 0; q < 4; q++) {
        float v = vs[q];
        __nv_bfloat16 h = __float2bfloat16(v);
        __nv_bfloat16 l = __float2bfloat16(v - __bfloat162float(h));
        g_Ah[o + q * 8] = __bfloat16_as_ushort(h);
        g_Al[o + q * 8] = __bfloat16_as_ushort(l);
    }
}

// ---------------------------------------------------------------------------
// prep_w: swizzled per-chunk B images: [Bh 4KB | Bl 4KB]
// ---------------------------------------------------------------------------
__global__ void prep_w(const float* __restrict__ w) {
    int idx = blockIdx.x * 256 + threadIdx.x;
    int co = idx & 127;
    int gk = idx >> 7;
    int cls = 0;
    while (gk >= c_cumK[cls + 1]) cls++;
    int lk = gk - c_cumK[cls];
    int t = lk >> 8, ci = lk & 255;
    int bd = (cls >> 2) & 1, bh = (cls >> 1) & 1, bw = cls & 1;
    int nh = 2 - bh, nw = 2 - bw;
    int tw = (nw == 2) ? (t & 1) : 0;
    int tt = (nw == 2) ? (t >> 1) : t;
    int th = (nh == 2) ? (tt & 1) : 0;
    int td = (nh == 2) ? (tt >> 1) : tt;
    int jd = bd ? 1 : td * 2;
    int jh = bh ? 1 : th * 2;
    int jw = bw ? 1 : tw * 2;
    float v = w[(size_t)(co * 256 + ci) * 27 + jd * 9 + jh * 3 + jw];
    __nv_bfloat16 h = __float2bfloat16(v);
    __nv_bfloat16 l = __float2bfloat16(v - __bfloat162float(h));
    int chunk = (c_cumK[cls] >> 4) + (lk >> 4);
    int kk = lk & 15;
    u32 so = sw_off((u32)co, (u32)(kk >> 3)) + (kk & 7) * 2;
    unsigned char* base = g_B + (size_t)chunk * 8192;
    *(u16*)(base + so)        = __bfloat16_as_ushort(h);
    *(u16*)(base + 4096 + so) = __bfloat16_as_ushort(l);
}

// ---------------------------------------------------------------------------
// gemm_hmma: merged all-class HMMA GEMM, 4-stage cp.async pipeline.
// Pass order AhBh, AlBh, AhBl with register reuse (live: acc64+af16+bf8).
// Epilogue: y rows stored [even-pw 18 | odd-pw 18] for coalesced stores.
// ---------------------------------------------------------------------------
#define NSTAGE 4
#define STG 16384
#define GEMM_SMEM (NSTAGE * STG)

__global__ void __launch_bounds__(256, 2) gemm_hmma() {
    extern __shared__ unsigned char sm[];
    const u32 smb = smem_u32(sm);

    const int bid = blockIdx.x;
    int cls = 0;
    while (bid >= c_cumB[cls + 1]) cls++;
    const int mtile = bid - c_cumB[cls];
    const int bd = (cls >> 2) & 1, bh = (cls >> 1) & 1, bw = cls & 1;
    const int nh = 2 - bh, nw = 2 - bw;
    const int Dc = 17 - bd, Hc = 17 - bh, Wc = 17 - bw;
    const int M = 8 * Dc * Hc * Wc;
    const int nCh = (c_cumK[cls + 1] - c_cumK[cls]) >> 4;
    const int chBase = c_cumK[cls] >> 4;
    const int blockM = mtile * 128;

    const int tid = threadIdx.x;
    const int mrow = tid & 127, khalf = tid >> 7;
    const int m = blockM + mrow;
    const bool mval = m < M;
    int mm = mval ? m : 0;
    int aw = mm % Wc; int tq = mm / Wc;
    int ah = tq % Hc; tq /= Hc;
    int ad = tq % Dc; int an = tq / Dc;

    const u32 stsA = sw_off((u32)mrow, (u32)khalf);
    const u32 stsB = (u32)tid * 16;

    auto issueStage = [&](int kb) {
        const u32 base = smb + (u32)(kb & 3) * STG;
        int t = kb >> 4;
        int tw = (nw == 2) ? (t & 1) : 0;
        int tt = (nw == 2) ? (t >> 1) : t;
        int th = (nh == 2) ? (tt & 1) : 0;
        int td = (nh == 2) ? (tt >> 1) : tt;
        int xd = ad + (bd ? 0 : td - 1);
        int xh = ah + (bh ? 0 : th - 1);
        int xw = aw + (bw ? 0 : tw - 1);
        bool v = mval && ((unsigned)xd < 16u) && ((unsigned)xh < 16u) && ((unsigned)xw < 16u);
        size_t o = ((size_t)(((kb & 15) * 2 + khalf) * 8 + an)) * 32768
                 + (size_t)(xd * 256 + xh * 16 + xw) * 8;
        u32 sz = v ? 16u : 0u;
        cpa16(base + stsA,        g_Ah + o, sz);
        cpa16(base + 4096 + stsA, g_Al + o, sz);
        const unsigned char* gb = g_B + (size_t)(chBase + kb) * 8192 + tid * 16;
        cpa16(base + 8192  + stsB, gb, 16);
        cpa16(base + 12288 + stsB, gb + 4096, 16);
        CP_COMMIT();
    };

    const int lane = tid & 31, wid = tid >> 5;
    const int wM = (wid >> 2) * 64, wN = (wid & 3) * 32;
    const u32 arow = lane & 15, au = lane >> 4;
    const u32 brow = ((lane >> 4) << 3) + (lane & 7), bu = (lane >> 3) & 1;

    float acc[4][4][4];
#pragma unroll
    for (int t = 0; t < 4; t++)
#pragma unroll
        for (int j = 0; j < 4; j++)
#pragma unroll
            for (int q = 0; q < 4; q++) acc[t][j][q] = 0.f;

    auto pass = [&](u32 af[4][4], u32 bf[2][4]) {
#pragma unroll
        for (int t = 0; t < 4; t++)
#pragma unroll
            for (int j = 0; j < 4; j++)
                mma16816(acc[t][j], af[t][0], af[t][1], af[t][2], af[t][3],
                         bf[j >> 1][(j & 1) * 2], bf[j >> 1][(j & 1) * 2 + 1]);
    };

    auto computeChunk = [&](int buf) {
        const u32 ob = smb + (u32)buf * STG;
        u32 af[4][4], bf[2][4];
        // AhBh
#pragma unroll
        for (int t = 0; t < 4; t++)
            ldm4(ob + sw_off(wM + t * 16 + arow, au), af[t][0], af[t][1], af[t][2], af[t][3]);
#pragma unroll
        for (int s = 0; s < 2; s++)
            ldm4(ob + 8192 + sw_off(wN + s * 16 + brow, bu), bf[s][0], bf[s][1], bf[s][2], bf[s][3]);
        pass(af, bf);
        // AlBh (af regs reused for Al)
#pragma unroll
        for (int t = 0; t < 4; t++)
            ldm4(ob + 4096 + sw_off(wM + t * 16 + arow, au), af[t][0], af[t][1], af[t][2], af[t][3]);
        pass(af, bf);
        // AhBl (bf regs reused for Bl, af reloaded with Ah)
#pragma unroll
        for (int s = 0; s < 2; s++)
            ldm4(ob + 12288 + sw_off(wN + s * 16 + brow, bu), bf[s][0], bf[s][1], bf[s][2], bf[s][3]);
#pragma unroll
        for (int t = 0; t < 4; t++)
            ldm4(ob + sw_off(wM + t * 16 + arow, au), af[t][0], af[t][1], af[t][2], af[t][3]);
        pass(af, bf);
    };

    issueStage(0); issueStage(1); issueStage(2);
    for (int kb = 0; kb < nCh; kb++) {
        CP_WAIT2();
        __syncthreads();
        if (kb + NSTAGE - 1 < nCh) issueStage(kb + NSTAGE - 1);
        else CP_COMMIT();
        computeChunk(kb & 3);
    }

    // epilogue -> y[n][co][pd][ph][bw*18 + w_] (pw-parity-split rows, coalesced)
    const int g = lane >> 2, tq4 = lane & 3;
#pragma unroll
    for (int t = 0; t < 4; t++) {
#pragma unroll
        for (int half = 0; half < 2; half++) {
            int mi = blockM + wM + t * 16 + g + half * 8;
            if (mi < M) {
                int w_ = mi % Wc; int q = mi / Wc;
                int h_ = q % Hc; q /= Hc;
                int d_ = q % Dc; int nb = q / Dc;
                int pd = 2 * d_ + bd, ph = 2 * h_ + bh;
                size_t base = (size_t)nb * 5018112 + (size_t)pd * 1188 + ph * 36
                            + bw * 18 + w_;
                int co0 = wN + tq4 * 2;
#pragma unroll
                for (int j = 0; j < 4; j++) {
                    size_t off = base + (size_t)(co0 + j * 8) * 39204;
                    g_y[off]         = acc[t][j][half * 2];
                    g_y[off + 39204] = acc[t][j][half * 2 + 1];
                }
            }
        }
    }
}

// ---------------------------------------------------------------------------
// fir_kernel: separable FIR [0.25,0.75,0.75,0.25]^3 + bias.
// Plane rows in gmem are [even18|odd18]; de-interleave on smem store.
// Register prefetch of plane pd+1 overlaps LDG latency with compute.
// ---------------------------------------------------------------------------
__global__ __launch_bounds__(1024) void fir_kernel(const float* __restrict__ bias,
                                                   float* __restrict__ out) {
    __shared__ float plane[33][36];
    __shared__ float tmp[33][33];

    const int blk = blockIdx.x;
    const int n = blk >> 7, co = blk & 127;
    const int tid = threadIdx.x;
    const int zh = tid >> 5, zw = tid & 31;

    const float* __restrict__ ybase = g_y + (size_t)(n * 128 + co) * 39204;
    const float bv = bias[co];
    float* __restrict__ op = out + (size_t)blk * 32768;

    // static de-interleave map for this thread's 1-2 plane elements
    const int e0 = tid;
    const int r0i = e0 / 36, c0 = e0 - r0i * 36;
    const int p0 = (c0 < 18) ? 2 * c0 : 2 * (c0 - 18) + 1;
    const int e1 = tid + 1024;
    const bool has1 = e1 < 1188;
    const int r1i = e1 / 36, c1 = e1 - r1i * 36;
    const int p1 = (c1 < 18) ? 2 * c1 : 2 * (c1 - 18) + 1;

    const float C0 = 0.25f, C1 = 0.75f;
    const float cw[4] = {C0, C1, C1, C0};
    float s0 = 0.f, s1 = 0.f, s2 = 0.f, s3 = 0.f;
    float v0 = 0.f, v1 = 0.f;

    // preload plane 0
    {
        const float* pl = ybase;
        v0 = pl[e0];
        if (has1) v1 = pl[e1];
    }

    for (int pd = 0; pd < 35; ++pd) {
        if (pd <= 32) {
            plane[r0i][p0] = v0;
            if (has1) plane[r1i][p1] = v1;
        }
        __syncthreads();

        if (pd + 1 <= 32) {                 // prefetch next plane (overlapped)
            const float* pl = ybase + (size_t)(pd + 1) * 1188;
            v0 = pl[e0];
            if (has1) v1 = pl[e1];
        }

        if (pd <= 32) {
            for (int e = tid; e < 1056; e += 1024) {    // 33 rows x 32 zw
                int ph = e >> 5, zww = e & 31;
                float rs = 0.f;
#pragma unroll
                for (int mw = 0; mw < 4; mw++) {
                    int pw = zww - 1 + mw;
                    if ((unsigned)pw < 33u) rs += cw[mw] * plane[ph][pw];
                }
                tmp[ph][zww] = rs;
            }
        }
        __syncthreads();

        float snew = 0.f;
        if (pd <= 32) {
#pragma unroll
            for (int mh = 0; mh < 4; mh++) {
                int ph = zh - 1 + mh;
                if ((unsigned)ph < 33u) snew += cw[mh] * tmp[ph][zw];
            }
        }
        s0 = s1; s1 = s2; s2 = s3; s3 = snew;

        if (pd >= 2 && pd <= 33) {
            int zd = pd - 2;
            float z = C0 * (s0 + s3) + C1 * (s1 + s2) + bv;
            op[(size_t)zd * 1024 + zh * 32 + zw] = z;
        }
    }
}

// ---------------------------------------------------------------------------
extern "C" void kernel_launch(void* const* d_in, const int* in_sizes, int n_in,
                              void* d_out, int out_size) {
    const float* x    = (const float*)d_in[0];
    const float* w    = (const float*)d_in[1];
    const float* bias = (const float*)d_in[2];
    float* out = (float*)d_out;

    cudaFuncSetAttribute(gemm_hmma, cudaFuncAttributeMaxDynamicSharedMemorySize, GEMM_SMEM);

    prep_x<<<8192, 256>>>(x);
    prep_w<<<3456, 256>>>(w);
    gemm_hmma<<<2247, 256, GEMM_SMEM>>>();
    fir_kernel<<<1024, 1024>>>(bias, out);
}